// round 1
// baseline (speedup 1.0000x reference)
#include <cuda_runtime.h>
#include <cuda_bf16.h>
#include <math.h>

#define BS   16
#define NA   8400
#define NMAX 64
#define NC   80
#define TOPK 13
#define EPSF 1e-9f
#define PIF  3.14159265358979323846f

// Output layout (flattened, concatenated in reference return order, all f32)
#define LAB_OFF 0
#define CIR_OFF (BS*NA)                 // 134400
#define SC_OFF  (CIR_OFF + BS*NA*3)     // 537600
#define FG_OFF  (SC_OFF  + BS*NA*NC)    // 11289600
#define TGT_OFF (FG_OFF  + BS*NA)       // 11424000

// ---- scratch (static device arrays; no allocation in kernel_launch) ----
__device__ float         g_ov[BS*NMAX*NA];   // overlaps * mask_valid
__device__ float         g_al[BS*NMAX*NA];   // align_metric
__device__ unsigned char g_mp[BS*NMAX*NA];   // mask_pos (0/1)
__device__ float         g_posal[BS*NMAX];
__device__ float         g_posov[BS*NMAX];
__device__ int           g_tgt[BS*NA];
__device__ unsigned char g_fg[BS*NA];
__device__ float         g_norm[BS*NA];
__device__ int           g_lab[BS*NA];

// ============================================================
// Kernel A: per (b, j, a) — overlaps + align_metric
// ============================================================
__global__ void kA(const float* __restrict__ ps, const float* __restrict__ pc,
                   const float* __restrict__ anc, const int* __restrict__ gl,
                   const float* __restrict__ gb, const float* __restrict__ mg)
{
    int a = blockIdx.x * blockDim.x + threadIdx.x;
    int j = blockIdx.y;
    int b = blockIdx.z;
    if (a >= NA) return;
    int row = b * NMAX + j;
    long base = (long)row * NA + a;

    float mgt = mg[row];
    float gx = gb[row*3+0], gy = gb[row*3+1], gr = gb[row*3+2];
    float ax = anc[a*2+0],  ay = anc[a*2+1];
    float dx = gx - ax, dy = gy - ay;
    float dist = sqrtf(dx*dx + dy*dy);

    if (!(mgt > 0.f) || !(dist <= gr)) {
        g_ov[base] = 0.f; g_al[base] = 0.f;
        return;
    }

    float px = pc[((long)b*NA + a)*3 + 0];
    float py = pc[((long)b*NA + a)*3 + 1];
    float pr = pc[((long)b*NA + a)*3 + 2];

    // circle IoU (matches reference formulas)
    float ddx = gx - px, ddy = gy - py;
    float d  = sqrtf(ddx*ddx + ddy*ddy + EPSF);
    float r1 = gr, r2 = pr;
    float a1 = PIF*r1*r1, a2 = PIF*r2*r2;
    float d2 = d*d;
    float cos1 = fminf(fmaxf((d2 + r1*r1 - r2*r2) / (2.f*d*r1 + EPSF), -1.f), 1.f);
    float cos2 = fminf(fmaxf((d2 + r2*r2 - r1*r1) / (2.f*d*r2 + EPSF), -1.f), 1.f);
    float tri  = fmaxf((r1+r2-d)*(d+r1-r2)*(d-r1+r2)*(d+r1+r2), 0.f);
    float lens = r1*r1*acosf(cos1) + r2*r2*acosf(cos2) - 0.5f*sqrtf(tri);
    float rmin = fminf(r1, r2);
    float inter = (d >= r1 + r2) ? 0.f
                : ((d <= fabsf(r1 - r2)) ? PIF*rmin*rmin : lens);
    float iou = inter / (a1 + a2 - inter + EPSF);

    int lab = gl[row]; lab = max(0, min(NC-1, lab));
    float sc = ps[((long)b*NA + a)*NC + lab];

    float o2 = iou*iou;
    float al = sc * (o2*o2*o2);   // score^1 * iou^6

    g_ov[base] = iou;
    g_al[base] = al;
}

// ============================================================
// Kernel B: per (b, j) — top-13 with (value desc, index asc) tie-break,
//           then mask_pos0 = topk ∧ in_gts  (mask_gt row gating)
// ============================================================
#define BTHREADS 256
#define NCAND    (BTHREADS*TOPK)

__global__ void kB(const float* __restrict__ anc, const float* __restrict__ gb,
                   const float* __restrict__ mg)
{
    const int row = blockIdx.x;          // b*NMAX + j
    const long base = (long)row * NA;
    const int t = threadIdx.x;

    // zero mask row
    for (int a = t; a < NA; a += BTHREADS) g_mp[base + a] = 0;

    if (!(mg[row] > 0.f)) return;        // uniform per block

    // per-thread register top-13 over strided anchors
    float lv[TOPK]; int li[TOPK];
    #pragma unroll
    for (int k = 0; k < TOPK; k++) { lv[k] = -1.f; li[k] = 0x7fffffff; }

    for (int a = t; a < NA; a += BTHREADS) {
        float v = g_al[base + a];
        if (v > lv[TOPK-1] || (v == lv[TOPK-1] && a < li[TOPK-1])) {
            lv[TOPK-1] = v; li[TOPK-1] = a;
            #pragma unroll
            for (int k = TOPK-1; k > 0; k--) {
                bool sw = (lv[k] > lv[k-1]) || (lv[k] == lv[k-1] && li[k] < li[k-1]);
                if (sw) {
                    float tv = lv[k]; lv[k] = lv[k-1]; lv[k-1] = tv;
                    int   ti = li[k]; li[k] = li[k-1]; li[k-1] = ti;
                }
            }
        }
    }

    __shared__ float sv[NCAND];
    __shared__ int   si[NCAND];
    __shared__ float rv[BTHREADS];
    __shared__ int   ri[BTHREADS];
    __shared__ int   rp[BTHREADS];
    __shared__ int   sel[TOPK];

    #pragma unroll
    for (int k = 0; k < TOPK; k++) { sv[t*TOPK + k] = lv[k]; si[t*TOPK + k] = li[k]; }
    __syncthreads();

    // 13 rounds of block argmax over the 3328 candidates
    for (int r = 0; r < TOPK; r++) {
        float bv = -2.f; int bi = 0x7fffffff; int bp = -1;
        for (int p = t; p < NCAND; p += BTHREADS) {
            float v = sv[p]; int i = si[p];
            if (v > bv || (v == bv && i < bi)) { bv = v; bi = i; bp = p; }
        }
        rv[t] = bv; ri[t] = bi; rp[t] = bp;
        __syncthreads();
        for (int s = BTHREADS/2; s > 0; s >>= 1) {
            if (t < s) {
                float v2 = rv[t+s]; int i2 = ri[t+s];
                if (v2 > rv[t] || (v2 == rv[t] && i2 < ri[t])) {
                    rv[t] = v2; ri[t] = i2; rp[t] = rp[t+s];
                }
            }
            __syncthreads();
        }
        if (t == 0) { sel[r] = ri[0]; sv[rp[0]] = -2.f; si[rp[0]] = 0x7fffffff; }
        __syncthreads();
    }

    // set mask_pos0 = 1 at selected anchors that are inside the GT circle
    if (t < TOPK) {
        int a = sel[t];
        float gx = gb[row*3+0], gy = gb[row*3+1], gr = gb[row*3+2];
        float dx = gx - anc[a*2+0], dy = gy - anc[a*2+1];
        float dist = sqrtf(dx*dx + dy*dy);
        if (dist <= gr) g_mp[base + a] = 1;
    }
}

// ============================================================
// Kernel C: per (b, a) — multi-GT resolution, fg_mask, target_gt_idx,
//           target_labels, target_circles
// ============================================================
__global__ void kC(const int* __restrict__ gl, const float* __restrict__ gb,
                   float* __restrict__ out)
{
    int a = blockIdx.x * blockDim.x + threadIdx.x;
    int b = blockIdx.y;
    if (a >= NA) return;
    long rb = (long)b * NMAX * NA + a;

    int fgc = 0, firstj = -1, jmax = 0;
    float bov = -1.f;
    for (int j = 0; j < NMAX; j++) {
        float ov = g_ov[rb + (long)j * NA];
        if (ov > bov) { bov = ov; jmax = j; }              // first-max semantics
        if (g_mp[rb + (long)j * NA]) { fgc++; if (firstj < 0) firstj = j; }
    }

    int fg, tgt;
    if (fgc > 1) {
        for (int j = 0; j < NMAX; j++)
            g_mp[rb + (long)j * NA] = (j == jmax) ? 1 : 0;
        fg = 1; tgt = jmax;
    } else {
        fg = fgc; tgt = (firstj >= 0) ? firstj : 0;
    }

    int pa = b * NA + a;
    g_tgt[pa] = tgt;
    g_fg[pa]  = (unsigned char)fg;

    int lab = gl[b*NMAX + tgt]; if (lab < 0) lab = 0;
    out[LAB_OFF + pa] = (float)lab;
    const float* c = &gb[(b*NMAX + tgt)*3];
    out[CIR_OFF + pa*3 + 0] = c[0];
    out[CIR_OFF + pa*3 + 1] = c[1];
    out[CIR_OFF + pa*3 + 2] = c[2];
    out[FG_OFF  + pa] = (float)fg;
    out[TGT_OFF + pa] = (float)tgt;
}

// ============================================================
// Kernel D: per (b, j) — pos_align, pos_overlaps (row maxima over anchors)
// ============================================================
__global__ void kD()
{
    const int row = blockIdx.x;
    const long base = (long)row * NA;
    const int t = threadIdx.x;
    float ma = 0.f, mo = 0.f;
    for (int a = t; a < NA; a += BTHREADS) {
        if (g_mp[base + a]) {
            ma = fmaxf(ma, g_al[base + a]);
            mo = fmaxf(mo, g_ov[base + a]);
        }
    }
    __shared__ float sa[BTHREADS], so[BTHREADS];
    sa[t] = ma; so[t] = mo;
    __syncthreads();
    for (int s = BTHREADS/2; s > 0; s >>= 1) {
        if (t < s) { sa[t] = fmaxf(sa[t], sa[t+s]); so[t] = fmaxf(so[t], so[t+s]); }
        __syncthreads();
    }
    if (t == 0) { g_posal[row] = sa[0]; g_posov[row] = so[0]; }
}

// ============================================================
// Kernel E: per (b, a) — norm (single positive GT per anchor) + label cache
// ============================================================
__global__ void kE(const int* __restrict__ gl)
{
    int a = blockIdx.x * blockDim.x + threadIdx.x;
    int b = blockIdx.y;
    if (a >= NA) return;
    int pa = b * NA + a;
    int tgt = g_tgt[pa];
    float nrm = 0.f; int lab = -1;
    if (g_fg[pa]) {
        int row = b * NMAX + tgt;
        long idx = (long)row * NA + a;
        nrm = g_al[idx] * g_posov[row] / (g_posal[row] + EPSF);
        lab = gl[row]; if (lab < 0) lab = 0;
    }
    g_norm[pa] = nrm;
    g_lab[pa]  = lab;
}

// ============================================================
// Kernel F: per (b, a, c) — target_scores scatter (coalesced)
// ============================================================
__global__ void kF(float* __restrict__ out)
{
    long idx = (long)blockIdx.x * blockDim.x + threadIdx.x;
    const long total = (long)BS * NA * NC;
    if (idx >= total) return;
    int pa = (int)(idx / NC);
    int c  = (int)(idx % NC);
    float v = (c == g_lab[pa]) ? g_norm[pa] : 0.f;
    out[SC_OFF + idx] = v;
}

// ============================================================
extern "C" void kernel_launch(void* const* d_in, const int* in_sizes, int n_in,
                              void* d_out, int out_size)
{
    const float* pd_scores  = (const float*)d_in[0];
    const float* pd_circles = (const float*)d_in[1];
    const float* anc_points = (const float*)d_in[2];
    const int*   gt_labels  = (const int*)  d_in[3];
    const float* gt_bboxes  = (const float*)d_in[4];
    const float* mask_gt    = (const float*)d_in[5];
    float* out = (float*)d_out;

    dim3 gA((NA + 255)/256, NMAX, BS);
    kA<<<gA, 256>>>(pd_scores, pd_circles, anc_points, gt_labels, gt_bboxes, mask_gt);

    kB<<<BS*NMAX, BTHREADS>>>(anc_points, gt_bboxes, mask_gt);

    dim3 gC((NA + 255)/256, BS);
    kC<<<gC, 256>>>(gt_labels, gt_bboxes, out);

    kD<<<BS*NMAX, BTHREADS>>>();

    kE<<<gC, 256>>>(gt_labels);

    long total = (long)BS * NA * NC;
    kF<<<(unsigned)((total + 255)/256), 256>>>(out);
}

// round 2
// speedup vs baseline: 2.2334x; 2.2334x over previous
#include <cuda_runtime.h>
#include <cuda_bf16.h>
#include <math.h>

#define BS   16
#define NA   8400
#define NMAX 64
#define NC   80
#define TOPK 13
#define EPSF 1e-9f
#define PIF  3.14159265358979323846f
#define TPB  256

// Output layout (flattened, concatenated in reference return order, all f32)
#define LAB_OFF 0
#define CIR_OFF (BS*NA)                 // 134400
#define SC_OFF  (CIR_OFF + BS*NA*3)     // 537600
#define FG_OFF  (SC_OFF  + BS*NA*NC)    // 11289600
#define TGT_OFF (FG_OFF  + BS*NA)       // 11424000

// ---- scratch ----
__device__ int          g_cnt [BS*NA];   // topk claims per anchor
__device__ int          g_minj[BS*NA];   // min claiming gt idx
__device__ int          g_tgt [BS*NA];   // resolved gt idx
__device__ int          g_lab [BS*NA];   // label for one-hot (-1 = background)
__device__ float        g_alpos[BS*NA];  // align metric at positive pair
__device__ unsigned int g_posal[BS*NMAX]; // row max align (float bits)
__device__ unsigned int g_posov[BS*NMAX]; // row max overlap (float bits)

__device__ __forceinline__ float circle_iou_f(float gx, float gy, float gr,
                                              float px, float py, float pr)
{
    float ddx = gx - px, ddy = gy - py;
    float d  = sqrtf(ddx*ddx + ddy*ddy + EPSF);
    float r1 = gr, r2 = pr;
    float a1 = PIF*r1*r1, a2 = PIF*r2*r2;
    float d2 = d*d;
    float cos1 = fminf(fmaxf((d2 + r1*r1 - r2*r2) / (2.f*d*r1 + EPSF), -1.f), 1.f);
    float cos2 = fminf(fmaxf((d2 + r2*r2 - r1*r1) / (2.f*d*r2 + EPSF), -1.f), 1.f);
    float tri  = fmaxf((r1+r2-d)*(d+r1-r2)*(d-r1+r2)*(d+r1+r2), 0.f);
    float lens = r1*r1*acosf(cos1) + r2*r2*acosf(cos2) - 0.5f*sqrtf(tri);
    float rmin = fminf(r1, r2);
    float inter = (d >= r1 + r2) ? 0.f
                : ((d <= fabsf(r1 - r2)) ? PIF*rmin*rmin : lens);
    return inter / (a1 + a2 - inter + EPSF);
}

// ============================================================
// kInit: reset per-anchor claim state and per-row maxima
// ============================================================
__global__ void kInit()
{
    int i = blockIdx.x * blockDim.x + threadIdx.x;
    if (i < BS*NA) { g_cnt[i] = 0; g_minj[i] = 0x7fffffff; }
    if (i < BS*NMAX) { g_posal[i] = 0u; g_posov[i] = 0u; }
}

// ============================================================
// kAB: per (b, j) row — fused metric build + exact top-13
//      ((value desc, index asc) total order) + claim scatter.
// ============================================================
__global__ void kAB(const float* __restrict__ ps, const float* __restrict__ pc,
                    const float* __restrict__ anc, const int* __restrict__ gl,
                    const float* __restrict__ gb, const float* __restrict__ mg)
{
    const int row = blockIdx.x;          // b*NMAX + j
    if (!(mg[row] > 0.f)) return;        // invalid GT row: contributes nothing
    const int b = row / NMAX;
    const int j = row % NMAX;
    const int t = threadIdx.x;

    const float gx = gb[row*3+0], gy = gb[row*3+1], gr = gb[row*3+2];
    int lab = gl[row]; lab = max(0, min(NC-1, lab));

    const float2* anc2 = (const float2*)anc;

    // per-thread register top-13 over strided anchors (incl. zero entries:
    // ties on value resolved by smaller anchor index, matching lax.top_k)
    float lv[TOPK]; int li[TOPK];
    #pragma unroll
    for (int k = 0; k < TOPK; k++) { lv[k] = -1.f; li[k] = 0x7fffffff; }

    for (int a = t; a < NA; a += TPB) {
        float2 ap = anc2[a];
        float dx = gx - ap.x, dy = gy - ap.y;
        float dist = sqrtf(dx*dx + dy*dy);
        float v = 0.f;
        if (dist <= gr) {
            float px = pc[((long)b*NA + a)*3 + 0];
            float py = pc[((long)b*NA + a)*3 + 1];
            float pr = pc[((long)b*NA + a)*3 + 2];
            float iou = circle_iou_f(gx, gy, gr, px, py, pr);
            float sc = ps[((long)b*NA + a)*NC + lab];
            float o2 = iou*iou;
            v = sc * (o2*o2*o2);
        }
        if (v > lv[TOPK-1] || (v == lv[TOPK-1] && a < li[TOPK-1])) {
            lv[TOPK-1] = v; li[TOPK-1] = a;
            #pragma unroll
            for (int k = TOPK-1; k > 0; k--) {
                bool sw = (lv[k] > lv[k-1]) || (lv[k] == lv[k-1] && li[k] < li[k-1]);
                if (sw) {
                    float tv = lv[k]; lv[k] = lv[k-1]; lv[k-1] = tv;
                    int   ti = li[k]; li[k] = li[k-1]; li[k-1] = ti;
                }
            }
        }
    }

    // tournament merge: 13 rounds of block argmax over thread heads
    __shared__ float cv[TPB*TOPK];
    __shared__ int   ci[TPB*TOPK];
    __shared__ float wv[8]; __shared__ int wi[8]; __shared__ int wt[8];
    __shared__ int   s_win;
    __shared__ int   s_sel[TOPK];

    #pragma unroll
    for (int k = 0; k < TOPK; k++) { cv[t*TOPK + k] = lv[k]; ci[t*TOPK + k] = li[k]; }
    __syncthreads();

    int head = 0;
    const int lane = t & 31, warp = t >> 5;

    for (int r = 0; r < TOPK; r++) {
        float v; int ii;
        if (head < TOPK) { v = cv[t*TOPK + head]; ii = ci[t*TOPK + head]; }
        else             { v = -2.f; ii = 0x7fffffff; }
        int who = t;
        #pragma unroll
        for (int off = 16; off > 0; off >>= 1) {
            float v2 = __shfl_down_sync(0xffffffffu, v, off);
            int   i2 = __shfl_down_sync(0xffffffffu, ii, off);
            int   w2 = __shfl_down_sync(0xffffffffu, who, off);
            if (v2 > v || (v2 == v && i2 < ii)) { v = v2; ii = i2; who = w2; }
        }
        if (lane == 0) { wv[warp] = v; wi[warp] = ii; wt[warp] = who; }
        __syncthreads();
        if (t < 8) {
            v = wv[t]; ii = wi[t]; who = wt[t];
            #pragma unroll
            for (int off = 4; off > 0; off >>= 1) {
                float v2 = __shfl_down_sync(0xffu, v, off);
                int   i2 = __shfl_down_sync(0xffu, ii, off);
                int   w2 = __shfl_down_sync(0xffu, who, off);
                if (v2 > v || (v2 == v && i2 < ii)) { v = v2; ii = i2; who = w2; }
            }
            if (t == 0) { s_win = who; s_sel[r] = ii; }
        }
        __syncthreads();
        if (t == s_win) head++;
    }

    // claim scatter: winners passing the inside-GT test become mask_pos0
    if (t < TOPK) {
        int a = s_sel[t];
        float2 ap = anc2[a];
        float dx = gx - ap.x, dy = gy - ap.y;
        if (sqrtf(dx*dx + dy*dy) <= gr) {
            int pa = b * NA + a;
            atomicAdd(&g_cnt[pa], 1);
            atomicMin(&g_minj[pa], j);
        }
    }
}

// ============================================================
// kC: per (b, a) — conflict resolution, gathers, row maxima
// ============================================================
__global__ void kC(const float* __restrict__ ps, const float* __restrict__ pc,
                   const float* __restrict__ anc, const int* __restrict__ gl,
                   const float* __restrict__ gb, const float* __restrict__ mg,
                   float* __restrict__ out)
{
    int a = blockIdx.x * blockDim.x + threadIdx.x;
    int b = blockIdx.y;
    if (a >= NA) return;
    int pa = b * NA + a;

    float ax = anc[a*2+0], ay = anc[a*2+1];
    float px = pc[(long)pa*3 + 0];
    float py = pc[(long)pa*3 + 1];
    float pr = pc[(long)pa*3 + 2];

    int cnt = g_cnt[pa];
    int tgt, fg;
    if (cnt > 1) {
        // argmax_j overlaps (first strict max, zeros for masked pairs)
        float bov = -1.f; int jm = 0;
        for (int jj = 0; jj < NMAX; jj++) {
            int row = b * NMAX + jj;
            float ov = 0.f;
            if (mg[row] > 0.f) {
                float gx = gb[row*3+0], gy = gb[row*3+1], gr = gb[row*3+2];
                float dx = gx - ax, dy = gy - ay;
                if (sqrtf(dx*dx + dy*dy) <= gr)
                    ov = circle_iou_f(gx, gy, gr, px, py, pr);
            }
            if (ov > bov) { bov = ov; jm = jj; }
        }
        tgt = jm; fg = 1;
    } else if (cnt == 1) {
        tgt = g_minj[pa]; fg = 1;
    } else {
        tgt = 0; fg = 0;
    }

    int row = b * NMAX + tgt;
    int labRaw = gl[row];
    int labOut = max(labRaw, 0);

    out[LAB_OFF + pa] = (float)labOut;
    out[CIR_OFF + pa*3 + 0] = gb[row*3+0];
    out[CIR_OFF + pa*3 + 1] = gb[row*3+1];
    out[CIR_OFF + pa*3 + 2] = gb[row*3+2];
    out[FG_OFF  + pa] = (float)fg;
    out[TGT_OFF + pa] = (float)tgt;

    g_tgt[pa] = tgt;
    float alv = 0.f;
    int labSc = -1;
    if (fg) {
        // recompute al/ov at the single winning pair (masked)
        float gx = gb[row*3+0], gy = gb[row*3+1], gr = gb[row*3+2];
        float dx = gx - ax, dy = gy - ay;
        float ov = 0.f;
        if (mg[row] > 0.f && sqrtf(dx*dx + dy*dy) <= gr)
            ov = circle_iou_f(gx, gy, gr, px, py, pr);
        int lc = max(0, min(NC-1, labRaw));
        float sc = ps[(long)pa*NC + lc];
        float o2 = ov*ov;
        alv = sc * (o2*o2*o2);
        labSc = labOut;
        if (alv > 0.f) atomicMax(&g_posal[row], __float_as_uint(alv));
        if (ov  > 0.f) atomicMax(&g_posov[row], __float_as_uint(ov));
    }
    g_alpos[pa] = alv;
    g_lab[pa]   = labSc;
}

// ============================================================
// kF: target_scores — float4 writes, norm computed inline
// ============================================================
__global__ void kF(float* __restrict__ out)
{
    int idx = blockIdx.x * blockDim.x + threadIdx.x;   // one float4 per thread
    const int total4 = BS * NA * (NC/4);
    if (idx >= total4) return;
    int pa = idx / (NC/4);
    int q  = idx - pa * (NC/4);

    int lab = g_lab[pa];
    float4 v = make_float4(0.f, 0.f, 0.f, 0.f);
    int c0 = q * 4;
    if (lab >= c0 && lab < c0 + 4) {
        int b = pa / NA;
        int row = b * NMAX + g_tgt[pa];
        float posal = __uint_as_float(g_posal[row]);
        float posov = __uint_as_float(g_posov[row]);
        float nrm = g_alpos[pa] * posov / (posal + EPSF);
        if (lab == c0)     v.x = nrm;
        else if (lab == c0+1) v.y = nrm;
        else if (lab == c0+2) v.z = nrm;
        else               v.w = nrm;
    }
    ((float4*)(out + SC_OFF))[idx] = v;
}

// ============================================================
extern "C" void kernel_launch(void* const* d_in, const int* in_sizes, int n_in,
                              void* d_out, int out_size)
{
    const float* pd_scores  = (const float*)d_in[0];
    const float* pd_circles = (const float*)d_in[1];
    const float* anc_points = (const float*)d_in[2];
    const int*   gt_labels  = (const int*)  d_in[3];
    const float* gt_bboxes  = (const float*)d_in[4];
    const float* mask_gt    = (const float*)d_in[5];
    float* out = (float*)d_out;

    kInit<<<(BS*NA + 255)/256, 256>>>();

    kAB<<<BS*NMAX, TPB>>>(pd_scores, pd_circles, anc_points,
                          gt_labels, gt_bboxes, mask_gt);

    dim3 gC((NA + 255)/256, BS);
    kC<<<gC, 256>>>(pd_scores, pd_circles, anc_points,
                    gt_labels, gt_bboxes, mask_gt, out);

    int total4 = BS * NA * (NC/4);
    kF<<<(total4 + 255)/256, 256>>>(out);
}